// round 2
// baseline (speedup 1.0000x reference)
#include <cuda_runtime.h>
#include <cstdint>

#define N_NODES 8192
#define C_CLS   16
#define ROWS_PER_BLK 512
#define COLS_PER_BLK 512
#define TPB 256

// Global scratch for cross-block reduction (no device mallocs allowed).
__device__ double g_quad;
__device__ double g_s;
__device__ double g_dH[C_CLS];

__global__ void mm_init() {
    int t = threadIdx.x;
    if (t == 0) { g_quad = 0.0; g_s = 0.0; }
    if (t < C_CLS) g_dH[t] = 0.0;
}

// Each block: columns [colbase, colbase+512) x rows [rowbase, rowbase+512).
// Lane owns 2 adjacent columns (j, j+1); accumulates x[j,:] = sum_i adj_ij * H[i,:]
// in 16 packed f32x2 registers per column, plus integer degree counts.
__global__ void __launch_bounds__(TPB) mm_main(const float* __restrict__ A,
                                               const float* __restrict__ H) {
    __shared__ float sh[ROWS_PER_BLK * C_CLS];   // 32 KB H row-chunk
    __shared__ float s_dH[C_CLS];
    __shared__ float s_quad;
    __shared__ unsigned int s_deg;

    const int t = threadIdx.x;
    const int colbase = blockIdx.x * COLS_PER_BLK;
    const int rowbase = blockIdx.y * ROWS_PER_BLK;

    if (t < C_CLS) s_dH[t] = 0.f;
    if (t == 0) { s_quad = 0.f; s_deg = 0u; }

    // Cooperative load of H rows [rowbase, rowbase+512) into SMEM (float4).
    {
        const float4* src = reinterpret_cast<const float4*>(H + (size_t)rowbase * C_CLS);
        float4* dst = reinterpret_cast<float4*>(sh);
        for (int k = t; k < ROWS_PER_BLK * C_CLS / 4; k += TPB) dst[k] = src[k];
    }
    __syncthreads();

    const int c0 = colbase + 2 * t;   // this lane's two columns: c0, c0+1

    unsigned long long acc0[8], acc1[8];   // packed f32x2 accumulators: x[c0,:], x[c0+1,:]
    #pragma unroll
    for (int k = 0; k < 8; k++) { acc0[k] = 0ull; acc1[k] = 0ull; }
    unsigned int deg0 = 0, deg1 = 0;

    const float2* __restrict__ arow =
        reinterpret_cast<const float2*>(A + (size_t)rowbase * N_NODES + c0);
    const size_t rstride = N_NODES / 2;   // row stride in float2 units

    #pragma unroll 4
    for (int i = 0; i < ROWS_PER_BLK; i++) {
        float2 av = __ldg(arow + (size_t)i * rstride);
        unsigned int p0 = (av.x > 0.f);
        unsigned int p1 = (av.y > 0.f);
        deg0 += p0; deg1 += p1;
        // mask as exact fp32 {0.0, 1.0}, duplicated into both f32x2 lanes
        unsigned int m0 = p0 ? 0x3f800000u : 0u;
        unsigned int m1 = p1 ? 0x3f800000u : 0u;
        unsigned long long mm0, mm1;
        asm("mov.b64 %0, {%1, %1};" : "=l"(mm0) : "r"(m0));
        asm("mov.b64 %0, {%1, %1};" : "=l"(mm1) : "r"(m1));
        const ulonglong2* hp = reinterpret_cast<const ulonglong2*>(sh + i * C_CLS);
        #pragma unroll
        for (int k = 0; k < 4; k++) {
            ulonglong2 h = hp[k];   // LDS.128, broadcast (all lanes same addr)
            asm("fma.rn.f32x2 %0, %1, %2, %0;" : "+l"(acc0[2*k])   : "l"(h.x), "l"(mm0));
            asm("fma.rn.f32x2 %0, %1, %2, %0;" : "+l"(acc0[2*k+1]) : "l"(h.y), "l"(mm0));
            asm("fma.rn.f32x2 %0, %1, %2, %0;" : "+l"(acc1[2*k])   : "l"(h.x), "l"(mm1));
            asm("fma.rn.f32x2 %0, %1, %2, %0;" : "+l"(acc1[2*k+1]) : "l"(h.y), "l"(mm1));
        }
    }

    // Epilogue: quad contribution = x[j] . H[j]; dH contribution = deg_j * H[j,:]
    const float* __restrict__ h0 = H + (size_t)c0 * C_CLS;
    const float* __restrict__ h1 = h0 + C_CLS;
    float q = 0.f;
    #pragma unroll
    for (int k = 0; k < 8; k++) {
        float x0lo = __uint_as_float((unsigned int)(acc0[k] & 0xffffffffull));
        float x0hi = __uint_as_float((unsigned int)(acc0[k] >> 32));
        float x1lo = __uint_as_float((unsigned int)(acc1[k] & 0xffffffffull));
        float x1hi = __uint_as_float((unsigned int)(acc1[k] >> 32));
        q += x0lo * h0[2*k] + x0hi * h0[2*k + 1];
        q += x1lo * h1[2*k] + x1hi * h1[2*k + 1];
    }
    atomicAdd(&s_quad, q);
    atomicAdd(&s_deg, deg0 + deg1);
    float fd0 = (float)deg0, fd1 = (float)deg1;
    #pragma unroll
    for (int c = 0; c < C_CLS; c++)
        atomicAdd(&s_dH[c], fd0 * h0[c] + fd1 * h1[c]);

    __syncthreads();
    if (t == 0) {
        atomicAdd(&g_quad, (double)s_quad);
        atomicAdd(&g_s, (double)s_deg);
    }
    if (t < C_CLS) atomicAdd(&g_dH[t], (double)s_dH[t]);
}

__global__ void mm_fin(float* out) {
    double s = g_s;
    double d = 0.0;
    #pragma unroll
    for (int c = 0; c < C_CLS; c++) d += g_dH[c] * g_dH[c];
    out[0] = (float)((g_quad - d / s) / s);
}

extern "C" void kernel_launch(void* const* d_in, const int* in_sizes, int n_in,
                              void* d_out, int out_size) {
    const float* H = nullptr;
    const float* A = nullptr;
    for (int i = 0; i < n_in; i++) {
        if (in_sizes[i] == N_NODES * C_CLS)      H = (const float*)d_in[i];
        else if (in_sizes[i] == N_NODES * N_NODES) A = (const float*)d_in[i];
    }
    mm_init<<<1, 32>>>();
    dim3 grid(N_NODES / COLS_PER_BLK, N_NODES / ROWS_PER_BLK);
    mm_main<<<grid, TPB>>>(A, H);
    mm_fin<<<1, 1>>>((float*)d_out);
}

// round 3
// speedup vs baseline: 1.4230x; 1.4230x over previous
#include <cuda_runtime.h>
#include <cstdint>

#define N_NODES 8192
#define C_CLS   16
#define ROWS_PER_BLK 256
#define COLS_PER_BLK 256
#define TPB 128
#define NBX (N_NODES / COLS_PER_BLK)   // 32
#define NBY (N_NODES / ROWS_PER_BLK)   // 32
#define NBLK (NBX * NBY)               // 1024

// Per-block partials: [0]=quad, [1]=deg, [2..17]=dH  (padded to 20)
__device__ float g_part[NBLK][20];

// Block: columns [colbase, colbase+256) x rows [rowbase, rowbase+256).
// Lane owns 2 adjacent columns; accumulates x[j,:] = sum_i adj_ij * H[i,:]
// in packed f32x2 registers + integer degree counts. MLP=8 via explicit
// prefetch batch of A values.
__global__ void __launch_bounds__(TPB) mm_main(const float* __restrict__ A,
                                               const float* __restrict__ H) {
    __shared__ float sh[ROWS_PER_BLK * C_CLS];   // 16 KB H row-chunk
    __shared__ float s_dH[C_CLS];
    __shared__ float s_quad;
    __shared__ unsigned int s_deg;

    const int t = threadIdx.x;
    const int colbase = blockIdx.x * COLS_PER_BLK;
    const int rowbase = blockIdx.y * ROWS_PER_BLK;

    if (t < C_CLS) s_dH[t] = 0.f;
    if (t == 0) { s_quad = 0.f; s_deg = 0u; }

    // Cooperative load of H rows [rowbase, rowbase+256) into SMEM (float4).
    {
        const float4* src = reinterpret_cast<const float4*>(H + (size_t)rowbase * C_CLS);
        float4* dst = reinterpret_cast<float4*>(sh);
        #pragma unroll
        for (int k = 0; k < (ROWS_PER_BLK * C_CLS / 4) / TPB; k++)   // 8
            dst[k * TPB + t] = src[k * TPB + t];
    }
    __syncthreads();

    const int c0 = colbase + 2 * t;   // this lane's two columns: c0, c0+1

    unsigned long long acc0[8], acc1[8];   // packed f32x2: x[c0,:], x[c0+1,:]
    #pragma unroll
    for (int k = 0; k < 8; k++) { acc0[k] = 0ull; acc1[k] = 0ull; }
    unsigned int deg0 = 0, deg1 = 0;

    const float2* __restrict__ arow =
        reinterpret_cast<const float2*>(A + (size_t)rowbase * N_NODES + c0);
    const size_t rs = N_NODES / 2;   // row stride in float2 units

    for (int i = 0; i < ROWS_PER_BLK; i += 8) {
        // Batched loads first: structural MLP = 8.
        float2 av[8];
        #pragma unroll
        for (int u = 0; u < 8; u++)
            av[u] = __ldg(arow + (size_t)(i + u) * rs);

        #pragma unroll
        for (int u = 0; u < 8; u++) {
            unsigned int p0 = (av[u].x > 0.f);
            unsigned int p1 = (av[u].y > 0.f);
            deg0 += p0; deg1 += p1;
            unsigned int m0 = p0 ? 0x3f800000u : 0u;   // exact {0.0f, 1.0f}
            unsigned int m1 = p1 ? 0x3f800000u : 0u;
            unsigned long long mm0, mm1;
            asm("mov.b64 %0, {%1, %1};" : "=l"(mm0) : "r"(m0));
            asm("mov.b64 %0, {%1, %1};" : "=l"(mm1) : "r"(m1));
            const ulonglong2* hp =
                reinterpret_cast<const ulonglong2*>(sh + (i + u) * C_CLS);
            #pragma unroll
            for (int k = 0; k < 4; k++) {
                ulonglong2 h = hp[k];   // LDS.128, broadcast across block
                asm("fma.rn.f32x2 %0, %1, %2, %0;" : "+l"(acc0[2*k])   : "l"(h.x), "l"(mm0));
                asm("fma.rn.f32x2 %0, %1, %2, %0;" : "+l"(acc0[2*k+1]) : "l"(h.y), "l"(mm0));
                asm("fma.rn.f32x2 %0, %1, %2, %0;" : "+l"(acc1[2*k])   : "l"(h.x), "l"(mm1));
                asm("fma.rn.f32x2 %0, %1, %2, %0;" : "+l"(acc1[2*k+1]) : "l"(h.y), "l"(mm1));
            }
        }
    }

    // Epilogue: quad += x[j].H[j];  dH += deg_j * H[j,:]
    const float* __restrict__ h0 = H + (size_t)c0 * C_CLS;
    const float* __restrict__ h1 = h0 + C_CLS;
    float q = 0.f;
    #pragma unroll
    for (int k = 0; k < 8; k++) {
        float x0lo = __uint_as_float((unsigned int)(acc0[k] & 0xffffffffull));
        float x0hi = __uint_as_float((unsigned int)(acc0[k] >> 32));
        float x1lo = __uint_as_float((unsigned int)(acc1[k] & 0xffffffffull));
        float x1hi = __uint_as_float((unsigned int)(acc1[k] >> 32));
        q += x0lo * h0[2*k] + x0hi * h0[2*k + 1];
        q += x1lo * h1[2*k] + x1hi * h1[2*k + 1];
    }
    atomicAdd(&s_quad, q);
    atomicAdd(&s_deg, deg0 + deg1);
    float fd0 = (float)deg0, fd1 = (float)deg1;
    #pragma unroll
    for (int c = 0; c < C_CLS; c++)
        atomicAdd(&s_dH[c], fd0 * h0[c] + fd1 * h1[c]);

    __syncthreads();
    const int bid = blockIdx.y * gridDim.x + blockIdx.x;
    if (t == 0) { g_part[bid][0] = s_quad; g_part[bid][1] = (float)s_deg; }
    if (t < C_CLS) g_part[bid][2 + t] = s_dH[t];
}

// Single-block reduction over 1024 partials (one thread per block slot).
__global__ void __launch_bounds__(NBLK) mm_fin(float* out) {
    __shared__ double sacc[18];
    const int t = threadIdx.x;
    if (t < 18) sacc[t] = 0.0;
    __syncthreads();

    float v[18];
    #pragma unroll
    for (int k = 0; k < 18; k++) v[k] = g_part[t][k];
    #pragma unroll
    for (int k = 0; k < 18; k++) {
        #pragma unroll
        for (int o = 16; o > 0; o >>= 1)
            v[k] += __shfl_xor_sync(0xffffffffu, v[k], o);
    }
    if ((t & 31) == 0) {
        #pragma unroll
        for (int k = 0; k < 18; k++) atomicAdd(&sacc[k], (double)v[k]);
    }
    __syncthreads();
    if (t == 0) {
        double quad = sacc[0], s = sacc[1], d = 0.0;
        #pragma unroll
        for (int c = 0; c < C_CLS; c++) d += sacc[2 + c] * sacc[2 + c];
        out[0] = (float)((quad - d / s) / s);
    }
}

extern "C" void kernel_launch(void* const* d_in, const int* in_sizes, int n_in,
                              void* d_out, int out_size) {
    const float* H = nullptr;
    const float* A = nullptr;
    for (int i = 0; i < n_in; i++) {
        if (in_sizes[i] == N_NODES * C_CLS)        H = (const float*)d_in[i];
        else if (in_sizes[i] == N_NODES * N_NODES) A = (const float*)d_in[i];
    }
    dim3 grid(NBX, NBY);
    mm_main<<<grid, TPB>>>(A, H);
    mm_fin<<<1, NBLK>>>((float*)d_out);
}